// round 15
// baseline (speedup 1.0000x reference)
#include <cuda_runtime.h>
#include <stdint.h>

#define NMAX   100000
#define EMAX   1600000
#define IN_C   128
#define HID_C  128
#define OUT_C  64

#define SCAN_B 256
#define NBLK   ((NMAX + SCAN_B - 1) / SCAN_B)   // 391

// ---------------------------------------------------------------------------
// Scratch (__device__ globals; ~111 MiB). Dataflow (no aliasing):
//   gemm1: x -> g_xws (UNSCALED x@W1)        [stream B]
//   agg1 : g_xws,dinv -> g_agg1              [split in 2, pipelined w/ gemm2]
//   gemm2: g_agg1 -> g_xws (dinv-scaled h@W2)
//   agg2 : g_xws -> out
// ---------------------------------------------------------------------------
__device__ float g_xws [(size_t)NMAX * HID_C];
__device__ float g_agg1[(size_t)NMAX * HID_C];
__device__ float g_dinv[NMAX];
__device__ int   g_deg [NMAX];
__device__ int   g_csr_off[NMAX];
__device__ int   g_cursor [NMAX];
__device__ int   g_csr_src[EMAX];
__device__ int   g_bsum[NBLK + 1];
__device__ int   g_is64;
__device__ float4 g_wf1[(IN_C / 8) * HID_C * 4];   // 128 KB
__device__ float4 g_wf2[(HID_C / 8) * OUT_C * 4];  //  64 KB

// ---------------------------------------------------------------------------
__device__ __forceinline__ int edge_at(const void* ei, int etot, int which, int idx) {
    if (g_is64)
        return (int)((const long long*)ei)[(size_t)which * etot + idx];
    else
        return ((const int*)ei)[(size_t)which * etot + idx];
}

__global__ void k_init(const int* ei32, int n) {
    int i = blockIdx.x * blockDim.x + threadIdx.x;
    if (i < n) g_deg[i] = 0;
    if (i == 0) {
        int ok64 = 1;
#pragma unroll
        for (int j = 0; j < 16; j++)
            if (ei32[2 * j + 1] != 0) ok64 = 0;
        g_is64 = ok64;
    }
}

__global__ void k_deg_count(const void* ei, int e) {
    int i = blockIdx.x * blockDim.x + threadIdx.x;
    if (i < e) atomicAdd(&g_deg[edge_at(ei, e, 1, i)], 1);
}

// ---------------------------------------------------------------------------
// 3-phase parallel exclusive scan (scanA also emits dinv)
// ---------------------------------------------------------------------------
__global__ void __launch_bounds__(SCAN_B) k_scanA(int n) {
    __shared__ int sh[SCAN_B / 32];
    int i = blockIdx.x * SCAN_B + threadIdx.x;
    int v = (i < n) ? g_deg[i] : 0;
    if (i < n) g_dinv[i] = rsqrtf((float)(v + 1));   // +1 self-loop
#pragma unroll
    for (int o = 16; o > 0; o >>= 1) v += __shfl_down_sync(0xffffffffu, v, o);
    if ((threadIdx.x & 31) == 0) sh[threadIdx.x >> 5] = v;
    __syncthreads();
    if (threadIdx.x < SCAN_B / 32) {
        int w = sh[threadIdx.x];
#pragma unroll
        for (int o = SCAN_B / 64; o > 0; o >>= 1)
            w += __shfl_down_sync(0xffffffffu, w, o, SCAN_B / 32);
        if (threadIdx.x == 0) g_bsum[blockIdx.x] = w;
    }
}

__global__ void __launch_bounds__(512) k_scanB(int nblk) {
    __shared__ int sh[512];
    int tid = threadIdx.x;
    int v = (tid < nblk) ? g_bsum[tid] : 0;
    sh[tid] = v;
    __syncthreads();
    for (int d = 1; d < 512; d <<= 1) {
        int t = (tid >= d) ? sh[tid - d] : 0;
        __syncthreads();
        sh[tid] += t;
        __syncthreads();
    }
    if (tid < nblk) g_bsum[tid] = sh[tid] - v;
}

__global__ void __launch_bounds__(SCAN_B) k_scanC(int n) {
    __shared__ int sh[SCAN_B];
    int i   = blockIdx.x * SCAN_B + threadIdx.x;
    int tid = threadIdx.x;
    int v = (i < n) ? g_deg[i] : 0;
    sh[tid] = v;
    __syncthreads();
    for (int d = 1; d < SCAN_B; d <<= 1) {
        int t = (tid >= d) ? sh[tid - d] : 0;
        __syncthreads();
        sh[tid] += t;
        __syncthreads();
    }
    if (i < n) {
        int off = g_bsum[blockIdx.x] + sh[tid] - v;
        g_csr_off[i] = off;
        g_cursor[i]  = off;
    }
}

__global__ void k_csr_build(const void* ei, int e) {
    int i = blockIdx.x * blockDim.x + threadIdx.x;
    if (i < e) {
        int s = edge_at(ei, e, 0, i);
        int d = edge_at(ei, e, 1, i);
        int slot = atomicAdd(&g_cursor[d], 1);
        g_csr_src[slot] = s;
    }
}

// ---------------------------------------------------------------------------
// TF32 helpers
// ---------------------------------------------------------------------------
__device__ __forceinline__ uint32_t f2tf32(float f) {
    uint32_t r;
    asm("cvt.rna.tf32.f32 %0, %1;" : "=r"(r) : "f"(f));
    return r;
}

__device__ __forceinline__ void mma_tf32(float* d, const uint32_t* a,
                                         const uint32_t* b) {
    asm volatile(
        "mma.sync.aligned.m16n8k8.row.col.f32.tf32.tf32.f32 "
        "{%0,%1,%2,%3}, {%4,%5,%6,%7}, {%8,%9}, {%0,%1,%2,%3};\n"
        : "+f"(d[0]), "+f"(d[1]), "+f"(d[2]), "+f"(d[3])
        : "r"(a[0]), "r"(a[1]), "r"(a[2]), "r"(a[3]), "r"(b[0]), "r"(b[1]));
}

template <int CIN, int COUT>
__global__ void k_wsplit(const float* __restrict__ W, float4* __restrict__ wf)
{
    int idx = blockIdx.x * blockDim.x + threadIdx.x;
    int total = (CIN / 8) * COUT * 4;
    if (idx >= total) return;
    int t  = idx & 3;
    int nb = (idx >> 2) % COUT;
    int ks = idx / (4 * COUT);
    int k0 = ks * 8;
    float w0 = W[(k0 + t)     * COUT + nb];
    float w1 = W[(k0 + t + 4) * COUT + nb];
    uint32_t b0 = f2tf32(w0), b1 = f2tf32(w1);
    float4 v;
    v.x = __uint_as_float(b0);
    v.y = __uint_as_float(b1);
    v.z = __uint_as_float(f2tf32(w0 - __uint_as_float(b0)));
    v.w = __uint_as_float(f2tf32(w1 - __uint_as_float(b1)));
    wf[idx] = v;
}

// ---------------------------------------------------------------------------
// MMA mainloop + epilogue.  SCALE_EPI: multiply rows by dinv (gemm2 only).
// ---------------------------------------------------------------------------
template <int CIN, int COUT, int SCALE_EPI>
__device__ __forceinline__ void mma_core(const float* As,
                                         const float4* __restrict__ wf,
                                         float* __restrict__ dst,
                                         int row0, int n, int tid)
{
    constexpr int PAD = 132;
    constexpr int NT  = COUT / 8;

    const int w    = tid >> 5;
    const int lane = tid & 31;
    const int g    = lane >> 2;
    const int t    = lane & 3;
    const int arow = w * 16;

    float acc[NT][4];
#pragma unroll
    for (int i = 0; i < NT; i++) {
        acc[i][0] = acc[i][1] = acc[i][2] = acc[i][3] = 0.f;
    }

#pragma unroll 2
    for (int ks = 0; ks < CIN / 8; ks++) {
        const int k0 = ks * 8;
        float a0 = As[(arow + g)     * PAD + k0 + t];
        float a1 = As[(arow + g + 8) * PAD + k0 + t];
        float a2 = As[(arow + g)     * PAD + k0 + t + 4];
        float a3 = As[(arow + g + 8) * PAD + k0 + t + 4];
        uint32_t ab[4] = { f2tf32(a0), f2tf32(a1), f2tf32(a2), f2tf32(a3) };
        uint32_t ar[4] = { f2tf32(a0 - __uint_as_float(ab[0])),
                           f2tf32(a1 - __uint_as_float(ab[1])),
                           f2tf32(a2 - __uint_as_float(ab[2])),
                           f2tf32(a3 - __uint_as_float(ab[3])) };
        const float4* wrow = wf + (size_t)ks * (COUT * 4);
#pragma unroll
        for (int nt = 0; nt < NT; nt++) {
            int nb = nt * 8 + g;
            float4 f = __ldg(&wrow[nb * 4 + t]);
            uint32_t bb[2]  = { __float_as_uint(f.x), __float_as_uint(f.y) };
            uint32_t br2[2] = { __float_as_uint(f.z), __float_as_uint(f.w) };
            mma_tf32(acc[nt], ab, bb);
            mma_tf32(acc[nt], ab, br2);
            mma_tf32(acc[nt], ar, bb);
        }
    }

    int r0 = row0 + arow + g;
    int r1 = r0 + 8;
    float d0 = 1.f, d1 = 1.f;
    if (SCALE_EPI) {
        d0 = (r0 < n) ? g_dinv[r0] : 0.f;
        d1 = (r1 < n) ? g_dinv[r1] : 0.f;
    }
#pragma unroll
    for (int nt = 0; nt < NT; nt++) {
        int col = nt * 8 + t * 2;
        if (r0 < n) {
            float2 v = make_float2(d0 * acc[nt][0], d0 * acc[nt][1]);
            *(float2*)(dst + (size_t)r0 * COUT + col) = v;
        }
        if (r1 < n) {
            float2 v = make_float2(d1 * acc[nt][2], d1 * acc[nt][3]);
            *(float2*)(dst + (size_t)r1 * COUT + col) = v;
        }
    }
}

// ---------------------------------------------------------------------------
// Layer-1 GEMM: g_xws = x @ W1  (UNSCALED; concurrent with preproc)
// ---------------------------------------------------------------------------
__global__ void __launch_bounds__(256)
k_gemm1(const float* __restrict__ X, const float4* __restrict__ wf, int n)
{
    constexpr int PAD = 132;
    extern __shared__ float As[];
    const int tid  = threadIdx.x;
    const int row0 = blockIdx.x * 128;

    for (int idx = tid; idx < 128 * (IN_C / 4); idx += 256) {
        int r  = idx / (IN_C / 4);
        int c4 = (idx - r * (IN_C / 4)) * 4;
        float4 v = make_float4(0.f, 0.f, 0.f, 0.f);
        if (row0 + r < n)
            v = *(const float4*)(X + (size_t)(row0 + r) * IN_C + c4);
        *(float4*)(As + r * PAD + c4) = v;
    }
    __syncthreads();
    mma_core<IN_C, HID_C, 0>(As, wf, g_xws, row0, n, tid);
}

// ---------------------------------------------------------------------------
// Layer-2 GEMM (row-range version for pipelining):
//   rows [row_base + blk*128, ...): g_xws = dinv * (relu(g_agg1 + b1) @ W2)
// ---------------------------------------------------------------------------
__global__ void __launch_bounds__(256)
k_gemm2(const float4* __restrict__ wf, const float* __restrict__ b1,
        int row_base, int n)
{
    constexpr int PAD = 132;
    extern __shared__ float As[];
    const int tid  = threadIdx.x;
    const int row0 = row_base + blockIdx.x * 128;

    for (int idx = tid; idx < 128 * (HID_C / 4); idx += 256) {
        int r  = idx / (HID_C / 4);
        int c4 = (idx - r * (HID_C / 4)) * 4;
        float4 v = make_float4(0.f, 0.f, 0.f, 0.f);
        if (row0 + r < n) {
            v = *(const float4*)(g_agg1 + (size_t)(row0 + r) * HID_C + c4);
            float4 b = *(const float4*)(b1 + c4);
            v.x = fmaxf(v.x + b.x, 0.f);
            v.y = fmaxf(v.y + b.y, 0.f);
            v.z = fmaxf(v.z + b.z, 0.f);
            v.w = fmaxf(v.w + b.w, 0.f);
        }
        *(float4*)(As + r * PAD + c4) = v;
    }
    __syncthreads();
    mma_core<HID_C, OUT_C, 1>(As, wf, g_xws, row0, n, tid);
}

// ---------------------------------------------------------------------------
// Pull aggregation (node-range version), 8-way unroll.
//   L==1: g_agg1[d] = dinv[d]*(sum_s dinv[s]*xw[s] + dinv[d]*xw[d])
//   L==2: out[d]    = b2 + dinv[d]*(sum + self)   (xw pre-scaled)
// ---------------------------------------------------------------------------
template <int C, int L>
__global__ void k_agg(float* __restrict__ extout, const float* __restrict__ b2,
                      int node_base, int lim)
{
    constexpr int LANES = C / 4;
    int node = node_base + blockIdx.x * blockDim.y + threadIdx.y;
    if (node >= lim) return;
    int lane = threadIdx.x;

    const float4* __restrict__ xw = (const float4*)g_xws;

    int beg = g_csr_off[node];
    int end = beg + g_deg[node];

    float dnode = g_dinv[node];
    float4 a = xw[(size_t)node * LANES + lane];     // self-loop term
    float sw = (L == 1) ? dnode : 1.f;
    float ax = sw * a.x, ay = sw * a.y, az = sw * a.z, aw = sw * a.w;

    int j = beg;
    for (; j + 8 <= end; j += 8) {
        int s0 = g_csr_src[j + 0];
        int s1 = g_csr_src[j + 1];
        int s2 = g_csr_src[j + 2];
        int s3 = g_csr_src[j + 3];
        int s4 = g_csr_src[j + 4];
        int s5 = g_csr_src[j + 5];
        int s6 = g_csr_src[j + 6];
        int s7 = g_csr_src[j + 7];
        float4 v0 = xw[(size_t)s0 * LANES + lane];
        float4 v1 = xw[(size_t)s1 * LANES + lane];
        float4 v2 = xw[(size_t)s2 * LANES + lane];
        float4 v3 = xw[(size_t)s3 * LANES + lane];
        float4 v4 = xw[(size_t)s4 * LANES + lane];
        float4 v5 = xw[(size_t)s5 * LANES + lane];
        float4 v6 = xw[(size_t)s6 * LANES + lane];
        float4 v7 = xw[(size_t)s7 * LANES + lane];
        if (L == 1) {
            float w0 = __ldg(&g_dinv[s0]), w1 = __ldg(&g_dinv[s1]);
            float w2 = __ldg(&g_dinv[s2]), w3 = __ldg(&g_dinv[s3]);
            float w4 = __ldg(&g_dinv[s4]), w5 = __ldg(&g_dinv[s5]);
            float w6 = __ldg(&g_dinv[s6]), w7 = __ldg(&g_dinv[s7]);
            ax += w0*v0.x + w1*v1.x + w2*v2.x + w3*v3.x
                + w4*v4.x + w5*v5.x + w6*v6.x + w7*v7.x;
            ay += w0*v0.y + w1*v1.y + w2*v2.y + w3*v3.y
                + w4*v4.y + w5*v5.y + w6*v6.y + w7*v7.y;
            az += w0*v0.z + w1*v1.z + w2*v2.z + w3*v3.z
                + w4*v4.z + w5*v5.z + w6*v6.z + w7*v7.z;
            aw += w0*v0.w + w1*v1.w + w2*v2.w + w3*v3.w
                + w4*v4.w + w5*v5.w + w6*v6.w + w7*v7.w;
        } else {
            ax += (v0.x + v1.x) + (v2.x + v3.x) + (v4.x + v5.x) + (v6.x + v7.x);
            ay += (v0.y + v1.y) + (v2.y + v3.y) + (v4.y + v5.y) + (v6.y + v7.y);
            az += (v0.z + v1.z) + (v2.z + v3.z) + (v4.z + v5.z) + (v6.z + v7.z);
            aw += (v0.w + v1.w) + (v2.w + v3.w) + (v4.w + v5.w) + (v6.w + v7.w);
        }
    }
    for (; j < end; ++j) {
        int s = g_csr_src[j];
        float4 v = xw[(size_t)s * LANES + lane];
        float w = (L == 1) ? __ldg(&g_dinv[s]) : 1.f;
        ax += w * v.x; ay += w * v.y; az += w * v.z; aw += w * v.w;
    }

    float4 r;
    if (L == 1) {
        r.x = dnode * ax; r.y = dnode * ay;
        r.z = dnode * az; r.w = dnode * aw;
        ((float4*)g_agg1)[(size_t)node * LANES + lane] = r;
    } else {
        const float4 bb = ((const float4*)b2)[lane];
        r.x = dnode * ax + bb.x;
        r.y = dnode * ay + bb.y;
        r.z = dnode * az + bb.z;
        r.w = dnode * aw + bb.w;
        ((float4*)extout)[(size_t)node * LANES + lane] = r;
    }
}

// ---------------------------------------------------------------------------
// Launch: two-stream fork/join + pipelined agg1/gemm2 halves.
// ---------------------------------------------------------------------------
extern "C" void kernel_launch(void* const* d_in, const int* in_sizes, int n_in,
                              void* d_out, int out_size)
{
    const float* x  = (const float*)d_in[0];
    const void*  ei = d_in[1];
    const float* W1 = (const float*)d_in[2];
    const float* b1 = (const float*)d_in[3];
    const float* W2 = (const float*)d_in[4];
    const float* b2 = (const float*)d_in[5];
    float*       out = (float*)d_out;

    const int n = in_sizes[0] / IN_C;     // 100000
    const int e = in_sizes[1] / 2;        // 1600000
    const int TB = 256;
    const int nblk = (n + SCAN_B - 1) / SCAN_B;

    // One-time resources (init-only; per-call work is identical).
    static cudaStream_t s2 = nullptr;
    static cudaEvent_t evFork = nullptr, evJoin = nullptr;
    static cudaEvent_t evAgg1A = nullptr, evG2A = nullptr;
    if (s2 == nullptr) {
        cudaStreamCreateWithFlags(&s2, cudaStreamNonBlocking);
        cudaEventCreateWithFlags(&evFork,  cudaEventDisableTiming);
        cudaEventCreateWithFlags(&evJoin,  cudaEventDisableTiming);
        cudaEventCreateWithFlags(&evAgg1A, cudaEventDisableTiming);
        cudaEventCreateWithFlags(&evG2A,   cudaEventDisableTiming);
    }

    const int smemA = 128 * 132 * 4;      // 67584 B dynamic
    cudaFuncSetAttribute(k_gemm1,
                         cudaFuncAttributeMaxDynamicSharedMemorySize, smemA);
    cudaFuncSetAttribute(k_gemm2,
                         cudaFuncAttributeMaxDynamicSharedMemorySize, smemA);

    float4* wf1;  cudaGetSymbolAddress((void**)&wf1, g_wf1);
    float4* wf2;  cudaGetSymbolAddress((void**)&wf2, g_wf2);
    const int gblk  = (n + 127) / 128;    // 782 row-tiles
    const int gblk1 = gblk / 2;           // 391 tiles in half 1
    const int half  = gblk1 * 128;        // 50048 rows
    const int gblk2 = gblk - gblk1;

    // ---- fork ----
    cudaEventRecord(evFork, 0);
    cudaStreamWaitEvent(s2, evFork, 0);

    // Stream B: weight splits + GEMM1 (needs only x, W)
    {
        const int t1 = (IN_C / 8) * HID_C * 4;
        const int t2 = (HID_C / 8) * OUT_C * 4;
        k_wsplit<IN_C, HID_C><<<(t1 + 255) / 256, 256, 0, s2>>>(W1, wf1);
        k_wsplit<HID_C, OUT_C><<<(t2 + 255) / 256, 256, 0, s2>>>(W2, wf2);
        k_gemm1<<<gblk, 256, smemA, s2>>>(x, wf1, n);
    }

    // Default stream: edge preprocessing
    k_init     <<<(n + TB - 1) / TB, TB>>>((const int*)ei, n);
    k_deg_count<<<(e + TB - 1) / TB, TB>>>(ei, e);
    k_scanA    <<<nblk, SCAN_B>>>(n);
    k_scanB    <<<1, 512>>>(nblk);
    k_scanC    <<<nblk, SCAN_B>>>(n);
    k_csr_build<<<(e + TB - 1) / TB, TB>>>(ei, e);

    // ---- join (gemm1 + csr both ready) ----
    cudaEventRecord(evJoin, s2);
    cudaStreamWaitEvent(0, evJoin, 0);

    // Pipelined: agg1_h1 -> {agg1_h2 (stream 0)  ||  gemm2_h1 (s2)}
    {
        dim3 blk(HID_C / 4, 8);
        const int nodesPerBlk = 8;
        k_agg<HID_C, 1><<<(half + nodesPerBlk - 1) / nodesPerBlk, blk>>>(
            nullptr, nullptr, 0, half);
        cudaEventRecord(evAgg1A, 0);

        // s2 runs gemm2 over half-1 rows while stream 0 aggregates half 2
        cudaStreamWaitEvent(s2, evAgg1A, 0);
        k_gemm2<<<gblk1, 256, smemA, s2>>>(wf2, b1, 0, n);

        k_agg<HID_C, 1><<<(n - half + nodesPerBlk - 1) / nodesPerBlk, blk>>>(
            nullptr, nullptr, half, n);
        k_gemm2<<<gblk2, 256, smemA>>>(wf2, b1, half, n);

        cudaEventRecord(evG2A, s2);
        cudaStreamWaitEvent(0, evG2A, 0);
    }

    // Final aggregation (needs ALL of gemm2's output)
    {
        dim3 blk(OUT_C / 4, 16);
        k_agg<OUT_C, 2><<<(n + 15) / 16, blk>>>(out, b2, 0, n);
    }
}

// round 16
// speedup vs baseline: 1.0563x; 1.0563x over previous
#include <cuda_runtime.h>
#include <stdint.h>

#define NMAX   100000
#define EMAX   1600000
#define IN_C   128
#define HID_C  128
#define OUT_C  64

#define SCAN_B 256
#define NBLK   ((NMAX + SCAN_B - 1) / SCAN_B)   // 391

// ---------------------------------------------------------------------------
// Scratch (__device__ globals; ~111 MiB). Dataflow (no aliasing):
//   gemm1: x -> g_xws (UNSCALED x@W1)        [stream B]
//   agg1 : g_xws,dinv -> g_agg1
//   gemm2: g_agg1 -> g_xws (dinv-scaled h@W2)
//   agg2 : g_xws -> out
// ---------------------------------------------------------------------------
__device__ float g_xws [(size_t)NMAX * HID_C];
__device__ float g_agg1[(size_t)NMAX * HID_C];
__device__ float g_dinv[NMAX];
__device__ int   g_deg [NMAX];
__device__ int   g_csr_off[NMAX];
__device__ int   g_cursor [NMAX];
__device__ int   g_csr_src[EMAX];
__device__ int   g_bsum[NBLK + 1];
__device__ int   g_is64;
__device__ float4 g_wf1[(IN_C / 8) * HID_C * 4];   // 128 KB
__device__ float4 g_wf2[(HID_C / 8) * OUT_C * 4];  //  64 KB

// ---------------------------------------------------------------------------
__device__ __forceinline__ int edge_at(const void* ei, int etot, int which, int idx) {
    if (g_is64)
        return (int)((const long long*)ei)[(size_t)which * etot + idx];
    else
        return ((const int*)ei)[(size_t)which * etot + idx];
}

__global__ void k_init(const int* ei32, int n) {
    int i = blockIdx.x * blockDim.x + threadIdx.x;
    if (i < n) g_deg[i] = 0;
    if (i == 0) {
        int ok64 = 1;
#pragma unroll
        for (int j = 0; j < 16; j++)
            if (ei32[2 * j + 1] != 0) ok64 = 0;
        g_is64 = ok64;
    }
}

// 2 edges per thread (paired loads coalesce; halves issue count)
__global__ void k_deg_count(const void* ei, int e) {
    int i = (blockIdx.x * blockDim.x + threadIdx.x) * 2;
    if (i + 1 < e) {
        int d0 = edge_at(ei, e, 1, i);
        int d1 = edge_at(ei, e, 1, i + 1);
        atomicAdd(&g_deg[d0], 1);
        atomicAdd(&g_deg[d1], 1);
    } else if (i < e) {
        atomicAdd(&g_deg[edge_at(ei, e, 1, i)], 1);
    }
}

// ---------------------------------------------------------------------------
// 3-phase parallel exclusive scan (scanA also emits dinv)
// ---------------------------------------------------------------------------
__global__ void __launch_bounds__(SCAN_B) k_scanA(int n) {
    __shared__ int sh[SCAN_B / 32];
    int i = blockIdx.x * SCAN_B + threadIdx.x;
    int v = (i < n) ? g_deg[i] : 0;
    if (i < n) g_dinv[i] = rsqrtf((float)(v + 1));   // +1 self-loop
#pragma unroll
    for (int o = 16; o > 0; o >>= 1) v += __shfl_down_sync(0xffffffffu, v, o);
    if ((threadIdx.x & 31) == 0) sh[threadIdx.x >> 5] = v;
    __syncthreads();
    if (threadIdx.x < SCAN_B / 32) {
        int w = sh[threadIdx.x];
#pragma unroll
        for (int o = SCAN_B / 64; o > 0; o >>= 1)
            w += __shfl_down_sync(0xffffffffu, w, o, SCAN_B / 32);
        if (threadIdx.x == 0) g_bsum[blockIdx.x] = w;
    }
}

__global__ void __launch_bounds__(512) k_scanB(int nblk) {
    __shared__ int sh[512];
    int tid = threadIdx.x;
    int v = (tid < nblk) ? g_bsum[tid] : 0;
    sh[tid] = v;
    __syncthreads();
    for (int d = 1; d < 512; d <<= 1) {
        int t = (tid >= d) ? sh[tid - d] : 0;
        __syncthreads();
        sh[tid] += t;
        __syncthreads();
    }
    if (tid < nblk) g_bsum[tid] = sh[tid] - v;
}

__global__ void __launch_bounds__(SCAN_B) k_scanC(int n) {
    __shared__ int sh[SCAN_B];
    int i   = blockIdx.x * SCAN_B + threadIdx.x;
    int tid = threadIdx.x;
    int v = (i < n) ? g_deg[i] : 0;
    sh[tid] = v;
    __syncthreads();
    for (int d = 1; d < SCAN_B; d <<= 1) {
        int t = (tid >= d) ? sh[tid - d] : 0;
        __syncthreads();
        sh[tid] += t;
        __syncthreads();
    }
    if (i < n) {
        int off = g_bsum[blockIdx.x] + sh[tid] - v;
        g_csr_off[i] = off;
        g_cursor[i]  = off;
    }
}

// 2 edges per thread
__global__ void k_csr_build(const void* ei, int e) {
    int i = (blockIdx.x * blockDim.x + threadIdx.x) * 2;
    if (i + 1 < e) {
        int s0 = edge_at(ei, e, 0, i);
        int s1 = edge_at(ei, e, 0, i + 1);
        int d0 = edge_at(ei, e, 1, i);
        int d1 = edge_at(ei, e, 1, i + 1);
        int p0 = atomicAdd(&g_cursor[d0], 1);
        int p1 = atomicAdd(&g_cursor[d1], 1);
        g_csr_src[p0] = s0;
        g_csr_src[p1] = s1;
    } else if (i < e) {
        int s = edge_at(ei, e, 0, i);
        int d = edge_at(ei, e, 1, i);
        int slot = atomicAdd(&g_cursor[d], 1);
        g_csr_src[slot] = s;
    }
}

// ---------------------------------------------------------------------------
// TF32 helpers
// ---------------------------------------------------------------------------
__device__ __forceinline__ uint32_t f2tf32(float f) {
    uint32_t r;
    asm("cvt.rna.tf32.f32 %0, %1;" : "=r"(r) : "f"(f));
    return r;
}

__device__ __forceinline__ void mma_tf32(float* d, const uint32_t* a,
                                         const uint32_t* b) {
    asm volatile(
        "mma.sync.aligned.m16n8k8.row.col.f32.tf32.tf32.f32 "
        "{%0,%1,%2,%3}, {%4,%5,%6,%7}, {%8,%9}, {%0,%1,%2,%3};\n"
        : "+f"(d[0]), "+f"(d[1]), "+f"(d[2]), "+f"(d[3])
        : "r"(a[0]), "r"(a[1]), "r"(a[2]), "r"(a[3]), "r"(b[0]), "r"(b[1]));
}

// Merged: splits BOTH weight matrices (W1 then W2) in one launch.
__global__ void k_wsplit_all(const float* __restrict__ W1,
                             const float* __restrict__ W2)
{
    const int T1 = (IN_C / 8) * HID_C * 4;    // 8192
    const int T2 = (HID_C / 8) * OUT_C * 4;   // 4096
    int idx = blockIdx.x * blockDim.x + threadIdx.x;

    const float* W;
    float4* wf;
    int COUT, li;
    if (idx < T1) {
        W = W1; wf = g_wf1; COUT = HID_C; li = idx;
    } else if (idx < T1 + T2) {
        W = W2; wf = g_wf2; COUT = OUT_C; li = idx - T1;
    } else {
        return;
    }

    int t  = li & 3;
    int nb = (li >> 2) % COUT;
    int ks = li / (4 * COUT);
    int k0 = ks * 8;
    float w0 = W[(k0 + t)     * COUT + nb];
    float w1 = W[(k0 + t + 4) * COUT + nb];
    uint32_t b0 = f2tf32(w0), b1 = f2tf32(w1);
    float4 v;
    v.x = __uint_as_float(b0);
    v.y = __uint_as_float(b1);
    v.z = __uint_as_float(f2tf32(w0 - __uint_as_float(b0)));
    v.w = __uint_as_float(f2tf32(w1 - __uint_as_float(b1)));
    wf[li] = v;
}

// ---------------------------------------------------------------------------
// MMA mainloop + epilogue.  SCALE_EPI: multiply rows by dinv (gemm2 only).
// ---------------------------------------------------------------------------
template <int CIN, int COUT, int SCALE_EPI>
__device__ __forceinline__ void mma_core(const float* As,
                                         const float4* __restrict__ wf,
                                         float* __restrict__ dst,
                                         int row0, int n, int tid)
{
    constexpr int PAD = 132;
    constexpr int NT  = COUT / 8;

    const int w    = tid >> 5;
    const int lane = tid & 31;
    const int g    = lane >> 2;
    const int t    = lane & 3;
    const int arow = w * 16;

    float acc[NT][4];
#pragma unroll
    for (int i = 0; i < NT; i++) {
        acc[i][0] = acc[i][1] = acc[i][2] = acc[i][3] = 0.f;
    }

#pragma unroll 2
    for (int ks = 0; ks < CIN / 8; ks++) {
        const int k0 = ks * 8;
        float a0 = As[(arow + g)     * PAD + k0 + t];
        float a1 = As[(arow + g + 8) * PAD + k0 + t];
        float a2 = As[(arow + g)     * PAD + k0 + t + 4];
        float a3 = As[(arow + g + 8) * PAD + k0 + t + 4];
        uint32_t ab[4] = { f2tf32(a0), f2tf32(a1), f2tf32(a2), f2tf32(a3) };
        uint32_t ar[4] = { f2tf32(a0 - __uint_as_float(ab[0])),
                           f2tf32(a1 - __uint_as_float(ab[1])),
                           f2tf32(a2 - __uint_as_float(ab[2])),
                           f2tf32(a3 - __uint_as_float(ab[3])) };
        const float4* wrow = wf + (size_t)ks * (COUT * 4);
#pragma unroll
        for (int nt = 0; nt < NT; nt++) {
            int nb = nt * 8 + g;
            float4 f = __ldg(&wrow[nb * 4 + t]);
            uint32_t bb[2]  = { __float_as_uint(f.x), __float_as_uint(f.y) };
            uint32_t br2[2] = { __float_as_uint(f.z), __float_as_uint(f.w) };
            mma_tf32(acc[nt], ab, bb);
            mma_tf32(acc[nt], ab, br2);
            mma_tf32(acc[nt], ar, bb);
        }
    }

    int r0 = row0 + arow + g;
    int r1 = r0 + 8;
    float d0 = 1.f, d1 = 1.f;
    if (SCALE_EPI) {
        d0 = (r0 < n) ? g_dinv[r0] : 0.f;
        d1 = (r1 < n) ? g_dinv[r1] : 0.f;
    }
#pragma unroll
    for (int nt = 0; nt < NT; nt++) {
        int col = nt * 8 + t * 2;
        if (r0 < n) {
            float2 v = make_float2(d0 * acc[nt][0], d0 * acc[nt][1]);
            *(float2*)(dst + (size_t)r0 * COUT + col) = v;
        }
        if (r1 < n) {
            float2 v = make_float2(d1 * acc[nt][2], d1 * acc[nt][3]);
            *(float2*)(dst + (size_t)r1 * COUT + col) = v;
        }
    }
}

// ---------------------------------------------------------------------------
// Layer-1 GEMM: g_xws = x @ W1  (UNSCALED; concurrent with preproc)
// ---------------------------------------------------------------------------
__global__ void __launch_bounds__(256)
k_gemm1(const float* __restrict__ X, const float4* __restrict__ wf, int n)
{
    constexpr int PAD = 132;
    extern __shared__ float As[];
    const int tid  = threadIdx.x;
    const int row0 = blockIdx.x * 128;

    for (int idx = tid; idx < 128 * (IN_C / 4); idx += 256) {
        int r  = idx / (IN_C / 4);
        int c4 = (idx - r * (IN_C / 4)) * 4;
        float4 v = make_float4(0.f, 0.f, 0.f, 0.f);
        if (row0 + r < n)
            v = *(const float4*)(X + (size_t)(row0 + r) * IN_C + c4);
        *(float4*)(As + r * PAD + c4) = v;
    }
    __syncthreads();
    mma_core<IN_C, HID_C, 0>(As, wf, g_xws, row0, n, tid);
}

// ---------------------------------------------------------------------------
// Layer-2 GEMM: g_xws = dinv * (relu(g_agg1 + b1) @ W2)
// ---------------------------------------------------------------------------
__global__ void __launch_bounds__(256)
k_gemm2(const float4* __restrict__ wf, const float* __restrict__ b1, int n)
{
    constexpr int PAD = 132;
    extern __shared__ float As[];
    const int tid  = threadIdx.x;
    const int row0 = blockIdx.x * 128;

    for (int idx = tid; idx < 128 * (HID_C / 4); idx += 256) {
        int r  = idx / (HID_C / 4);
        int c4 = (idx - r * (HID_C / 4)) * 4;
        float4 v = make_float4(0.f, 0.f, 0.f, 0.f);
        if (row0 + r < n) {
            v = *(const float4*)(g_agg1 + (size_t)(row0 + r) * HID_C + c4);
            float4 b = *(const float4*)(b1 + c4);
            v.x = fmaxf(v.x + b.x, 0.f);
            v.y = fmaxf(v.y + b.y, 0.f);
            v.z = fmaxf(v.z + b.z, 0.f);
            v.w = fmaxf(v.w + b.w, 0.f);
        }
        *(float4*)(As + r * PAD + c4) = v;
    }
    __syncthreads();
    mma_core<HID_C, OUT_C, 1>(As, wf, g_xws, row0, n, tid);
}

// ---------------------------------------------------------------------------
// Pull aggregation, 8-way unroll.
//   L==1: src g_xws is UNSCALED -> apply dinv[s] per source.
//         g_agg1 = dinv[d] * (sum_s dinv[s]*xw[s] + dinv[d]*xw[d])
//   L==2: src g_xws is pre-scaled. out = b2 + dinv[d]*(sum + self)
// ---------------------------------------------------------------------------
template <int C, int L>
__global__ void k_agg(float* __restrict__ extout, const float* __restrict__ b2,
                      int n)
{
    constexpr int LANES = C / 4;
    int node = blockIdx.x * blockDim.y + threadIdx.y;
    if (node >= n) return;
    int lane = threadIdx.x;

    const float4* __restrict__ xw = (const float4*)g_xws;

    int beg = g_csr_off[node];
    int end = beg + g_deg[node];

    float dnode = g_dinv[node];
    float4 a = xw[(size_t)node * LANES + lane];     // self-loop term
    float sw = (L == 1) ? dnode : 1.f;
    float ax = sw * a.x, ay = sw * a.y, az = sw * a.z, aw = sw * a.w;

    int j = beg;
    for (; j + 8 <= end; j += 8) {
        int s0 = g_csr_src[j + 0];
        int s1 = g_csr_src[j + 1];
        int s2 = g_csr_src[j + 2];
        int s3 = g_csr_src[j + 3];
        int s4 = g_csr_src[j + 4];
        int s5 = g_csr_src[j + 5];
        int s6 = g_csr_src[j + 6];
        int s7 = g_csr_src[j + 7];
        float4 v0 = xw[(size_t)s0 * LANES + lane];
        float4 v1 = xw[(size_t)s1 * LANES + lane];
        float4 v2 = xw[(size_t)s2 * LANES + lane];
        float4 v3 = xw[(size_t)s3 * LANES + lane];
        float4 v4 = xw[(size_t)s4 * LANES + lane];
        float4 v5 = xw[(size_t)s5 * LANES + lane];
        float4 v6 = xw[(size_t)s6 * LANES + lane];
        float4 v7 = xw[(size_t)s7 * LANES + lane];
        if (L == 1) {
            float w0 = __ldg(&g_dinv[s0]), w1 = __ldg(&g_dinv[s1]);
            float w2 = __ldg(&g_dinv[s2]), w3 = __ldg(&g_dinv[s3]);
            float w4 = __ldg(&g_dinv[s4]), w5 = __ldg(&g_dinv[s5]);
            float w6 = __ldg(&g_dinv[s6]), w7 = __ldg(&g_dinv[s7]);
            ax += w0*v0.x + w1*v1.x + w2*v2.x + w3*v3.x
                + w4*v4.x + w5*v5.x + w6*v6.x + w7*v7.x;
            ay += w0*v0.y + w1*v1.y + w2*v2.y + w3*v3.y
                + w4*v4.y + w5*v5.y + w6*v6.y + w7*v7.y;
            az += w0*v0.z + w1*v1.z + w2*v2.z + w3*v3.z
                + w4*v4.z + w5*v5.z + w6*v6.z + w7*v7.z;
            aw += w0*v0.w + w1*v1.w + w2*v2.w + w3*v3.w
                + w4*v4.w + w5*v5.w + w6*v6.w + w7*v7.w;
        } else {
            ax += (v0.x + v1.x) + (v2.x + v3.x) + (v4.x + v5.x) + (v6.x + v7.x);
            ay += (v0.y + v1.y) + (v2.y + v3.y) + (v4.y + v5.y) + (v6.y + v7.y);
            az += (v0.z + v1.z) + (v2.z + v3.z) + (v4.z + v5.z) + (v6.z + v7.z);
            aw += (v0.w + v1.w) + (v2.w + v3.w) + (v4.w + v5.w) + (v6.w + v7.w);
        }
    }
    for (; j < end; ++j) {
        int s = g_csr_src[j];
        float4 v = xw[(size_t)s * LANES + lane];
        float w = (L == 1) ? __ldg(&g_dinv[s]) : 1.f;
        ax += w * v.x; ay += w * v.y; az += w * v.z; aw += w * v.w;
    }

    float4 r;
    if (L == 1) {
        r.x = dnode * ax; r.y = dnode * ay;
        r.z = dnode * az; r.w = dnode * aw;
        ((float4*)g_agg1)[(size_t)node * LANES + lane] = r;
    } else {
        const float4 bb = ((const float4*)b2)[lane];
        r.x = dnode * ax + bb.x;
        r.y = dnode * ay + bb.y;
        r.z = dnode * az + bb.z;
        r.w = dnode * aw + bb.w;
        ((float4*)extout)[(size_t)node * LANES + lane] = r;
    }
}

// ---------------------------------------------------------------------------
// Launch: round-14 proven structure (fork/join; NO post-join concurrency).
// ---------------------------------------------------------------------------
extern "C" void kernel_launch(void* const* d_in, const int* in_sizes, int n_in,
                              void* d_out, int out_size)
{
    const float* x  = (const float*)d_in[0];
    const void*  ei = d_in[1];
    const float* W1 = (const float*)d_in[2];
    const float* b1 = (const float*)d_in[3];
    const float* W2 = (const float*)d_in[4];
    const float* b2 = (const float*)d_in[5];
    float*       out = (float*)d_out;

    const int n = in_sizes[0] / IN_C;     // 100000
    const int e = in_sizes[1] / 2;        // 1600000
    const int TB = 256;
    const int nblk = (n + SCAN_B - 1) / SCAN_B;

    // One-time resources (init-only; per-call work is identical).
    static cudaStream_t s2 = nullptr;
    static cudaEvent_t evFork = nullptr, evJoin = nullptr;
    if (s2 == nullptr) {
        cudaStreamCreateWithFlags(&s2, cudaStreamNonBlocking);
        cudaEventCreateWithFlags(&evFork, cudaEventDisableTiming);
        cudaEventCreateWithFlags(&evJoin, cudaEventDisableTiming);
    }

    const int smemA = 128 * 132 * 4;      // 67584 B dynamic
    cudaFuncSetAttribute(k_gemm1,
                         cudaFuncAttributeMaxDynamicSharedMemorySize, smemA);
    cudaFuncSetAttribute(k_gemm2,
                         cudaFuncAttributeMaxDynamicSharedMemorySize, smemA);

    const int gblk = (n + 127) / 128;

    // ---- fork ----
    cudaEventRecord(evFork, 0);
    cudaStreamWaitEvent(s2, evFork, 0);

    // Stream B: merged weight split + GEMM1 (needs only x, W)
    {
        const int tw = (IN_C / 8) * HID_C * 4 + (HID_C / 8) * OUT_C * 4;
        float4* wf1;  cudaGetSymbolAddress((void**)&wf1, g_wf1);
        k_wsplit_all<<<(tw + 255) / 256, 256, 0, s2>>>(W1, W2);
        k_gemm1<<<gblk, 256, smemA, s2>>>(x, wf1, n);
    }

    // Default stream: edge preprocessing (2 edges/thread in atomic passes)
    k_init     <<<(n + TB - 1) / TB, TB>>>((const int*)ei, n);
    k_deg_count<<<(e / 2 + TB - 1) / TB, TB>>>(ei, e);
    k_scanA    <<<nblk, SCAN_B>>>(n);
    k_scanB    <<<1, 512>>>(nblk);
    k_scanC    <<<nblk, SCAN_B>>>(n);
    k_csr_build<<<(e / 2 + TB - 1) / TB, TB>>>(ei, e);

    // ---- join ----
    cudaEventRecord(evJoin, s2);
    cudaStreamWaitEvent(0, evJoin, 0);

    // Layer 1 aggregation (alone, full L2 bandwidth)
    {
        dim3 blk(HID_C / 4, 8);
        k_agg<HID_C, 1><<<(n + 7) / 8, blk>>>(nullptr, nullptr, n);
    }

    // Layer 2
    {
        float4* wf2;  cudaGetSymbolAddress((void**)&wf2, g_wf2);
        k_gemm2<<<gblk, 256, smemA>>>(wf2, b1, n);
    }
    {
        dim3 blk(OUT_C / 4, 16);
        k_agg<OUT_C, 2><<<(n + 15) / 16, blk>>>(out, b2, n);
    }
}

// round 17
// speedup vs baseline: 1.1687x; 1.1064x over previous
#include <cuda_runtime.h>
#include <cuda_fp16.h>
#include <stdint.h>

#define NMAX   100000
#define EMAX   1600000
#define IN_C   128
#define HID_C  128
#define OUT_C  64

#define SCAN_B 256
#define NBLK   ((NMAX + SCAN_B - 1) / SCAN_B)   // 391

// ---------------------------------------------------------------------------
// Scratch. g_xws16: HALF-precision gathered feature buffer (both layers) —
// halves the agg gather traffic; accumulation stays fp32.  g_agg1 stays fp32
// (streamed, not gathered; only one fp16 quantization per layer).
// Total ~86 MiB.
// ---------------------------------------------------------------------------
__device__ __half g_xws16[(size_t)NMAX * HID_C];   // 25.6 MB
__device__ float  g_agg1 [(size_t)NMAX * HID_C];   // 51.2 MB
__device__ float  g_dinv[NMAX];
__device__ int    g_deg [NMAX];
__device__ int    g_csr_off[NMAX];
__device__ int    g_cursor [NMAX];
__device__ int    g_csr_src[EMAX];
__device__ int    g_bsum[NBLK + 1];
__device__ int    g_is64;
__device__ float4 g_wf1[(IN_C / 8) * HID_C * 4];   // 128 KB
__device__ float4 g_wf2[(HID_C / 8) * OUT_C * 4];  //  64 KB

// ---------------------------------------------------------------------------
__device__ __forceinline__ int edge_at(const void* ei, int etot, int which, int idx) {
    if (g_is64)
        return (int)((const long long*)ei)[(size_t)which * etot + idx];
    else
        return ((const int*)ei)[(size_t)which * etot + idx];
}

__global__ void k_init(const int* ei32, int n) {
    int i = blockIdx.x * blockDim.x + threadIdx.x;
    if (i < n) g_deg[i] = 0;
    if (i == 0) {
        int ok64 = 1;
#pragma unroll
        for (int j = 0; j < 16; j++)
            if (ei32[2 * j + 1] != 0) ok64 = 0;
        g_is64 = ok64;
    }
}

// 2 edges per thread
__global__ void k_deg_count(const void* ei, int e) {
    int i = (blockIdx.x * blockDim.x + threadIdx.x) * 2;
    if (i + 1 < e) {
        int d0 = edge_at(ei, e, 1, i);
        int d1 = edge_at(ei, e, 1, i + 1);
        atomicAdd(&g_deg[d0], 1);
        atomicAdd(&g_deg[d1], 1);
    } else if (i < e) {
        atomicAdd(&g_deg[edge_at(ei, e, 1, i)], 1);
    }
}

// ---------------------------------------------------------------------------
// 3-phase parallel exclusive scan (scanA also emits dinv)
// ---------------------------------------------------------------------------
__global__ void __launch_bounds__(SCAN_B) k_scanA(int n) {
    __shared__ int sh[SCAN_B / 32];
    int i = blockIdx.x * SCAN_B + threadIdx.x;
    int v = (i < n) ? g_deg[i] : 0;
    if (i < n) g_dinv[i] = rsqrtf((float)(v + 1));   // +1 self-loop
#pragma unroll
    for (int o = 16; o > 0; o >>= 1) v += __shfl_down_sync(0xffffffffu, v, o);
    if ((threadIdx.x & 31) == 0) sh[threadIdx.x >> 5] = v;
    __syncthreads();
    if (threadIdx.x < SCAN_B / 32) {
        int w = sh[threadIdx.x];
#pragma unroll
        for (int o = SCAN_B / 64; o > 0; o >>= 1)
            w += __shfl_down_sync(0xffffffffu, w, o, SCAN_B / 32);
        if (threadIdx.x == 0) g_bsum[blockIdx.x] = w;
    }
}

__global__ void __launch_bounds__(512) k_scanB(int nblk) {
    __shared__ int sh[512];
    int tid = threadIdx.x;
    int v = (tid < nblk) ? g_bsum[tid] : 0;
    sh[tid] = v;
    __syncthreads();
    for (int d = 1; d < 512; d <<= 1) {
        int t = (tid >= d) ? sh[tid - d] : 0;
        __syncthreads();
        sh[tid] += t;
        __syncthreads();
    }
    if (tid < nblk) g_bsum[tid] = sh[tid] - v;
}

__global__ void __launch_bounds__(SCAN_B) k_scanC(int n) {
    __shared__ int sh[SCAN_B];
    int i   = blockIdx.x * SCAN_B + threadIdx.x;
    int tid = threadIdx.x;
    int v = (i < n) ? g_deg[i] : 0;
    sh[tid] = v;
    __syncthreads();
    for (int d = 1; d < SCAN_B; d <<= 1) {
        int t = (tid >= d) ? sh[tid - d] : 0;
        __syncthreads();
        sh[tid] += t;
        __syncthreads();
    }
    if (i < n) {
        int off = g_bsum[blockIdx.x] + sh[tid] - v;
        g_csr_off[i] = off;
        g_cursor[i]  = off;
    }
}

// 2 edges per thread
__global__ void k_csr_build(const void* ei, int e) {
    int i = (blockIdx.x * blockDim.x + threadIdx.x) * 2;
    if (i + 1 < e) {
        int s0 = edge_at(ei, e, 0, i);
        int s1 = edge_at(ei, e, 0, i + 1);
        int d0 = edge_at(ei, e, 1, i);
        int d1 = edge_at(ei, e, 1, i + 1);
        int p0 = atomicAdd(&g_cursor[d0], 1);
        int p1 = atomicAdd(&g_cursor[d1], 1);
        g_csr_src[p0] = s0;
        g_csr_src[p1] = s1;
    } else if (i < e) {
        int s = edge_at(ei, e, 0, i);
        int d = edge_at(ei, e, 1, i);
        int slot = atomicAdd(&g_cursor[d], 1);
        g_csr_src[slot] = s;
    }
}

// ---------------------------------------------------------------------------
// TF32 helpers
// ---------------------------------------------------------------------------
__device__ __forceinline__ uint32_t f2tf32(float f) {
    uint32_t r;
    asm("cvt.rna.tf32.f32 %0, %1;" : "=r"(r) : "f"(f));
    return r;
}

__device__ __forceinline__ void mma_tf32(float* d, const uint32_t* a,
                                         const uint32_t* b) {
    asm volatile(
        "mma.sync.aligned.m16n8k8.row.col.f32.tf32.tf32.f32 "
        "{%0,%1,%2,%3}, {%4,%5,%6,%7}, {%8,%9}, {%0,%1,%2,%3};\n"
        : "+f"(d[0]), "+f"(d[1]), "+f"(d[2]), "+f"(d[3])
        : "r"(a[0]), "r"(a[1]), "r"(a[2]), "r"(a[3]), "r"(b[0]), "r"(b[1]));
}

// Merged: splits BOTH weight matrices in one launch.
__global__ void k_wsplit_all(const float* __restrict__ W1,
                             const float* __restrict__ W2)
{
    const int T1 = (IN_C / 8) * HID_C * 4;    // 8192
    const int T2 = (HID_C / 8) * OUT_C * 4;   // 4096
    int idx = blockIdx.x * blockDim.x + threadIdx.x;

    const float* W;
    float4* wf;
    int COUT, li;
    if (idx < T1) {
        W = W1; wf = g_wf1; COUT = HID_C; li = idx;
    } else if (idx < T1 + T2) {
        W = W2; wf = g_wf2; COUT = OUT_C; li = idx - T1;
    } else {
        return;
    }

    int t  = li & 3;
    int nb = (li >> 2) % COUT;
    int ks = li / (4 * COUT);
    int k0 = ks * 8;
    float w0 = W[(k0 + t)     * COUT + nb];
    float w1 = W[(k0 + t + 4) * COUT + nb];
    uint32_t b0 = f2tf32(w0), b1 = f2tf32(w1);
    float4 v;
    v.x = __uint_as_float(b0);
    v.y = __uint_as_float(b1);
    v.z = __uint_as_float(f2tf32(w0 - __uint_as_float(b0)));
    v.w = __uint_as_float(f2tf32(w1 - __uint_as_float(b1)));
    wf[li] = v;
}

// ---------------------------------------------------------------------------
// MMA mainloop + epilogue.  Emits __half2 into g_xws16 (stride COUT).
// SCALE_EPI: multiply rows by dinv (gemm2 only).
// ---------------------------------------------------------------------------
template <int CIN, int COUT, int SCALE_EPI>
__device__ __forceinline__ void mma_core(const float* As,
                                         const float4* __restrict__ wf,
                                         int row0, int n, int tid)
{
    constexpr int PAD = 132;
    constexpr int NT  = COUT / 8;

    const int w    = tid >> 5;
    const int lane = tid & 31;
    const int g    = lane >> 2;
    const int t    = lane & 3;
    const int arow = w * 16;

    float acc[NT][4];
#pragma unroll
    for (int i = 0; i < NT; i++) {
        acc[i][0] = acc[i][1] = acc[i][2] = acc[i][3] = 0.f;
    }

#pragma unroll 2
    for (int ks = 0; ks < CIN / 8; ks++) {
        const int k0 = ks * 8;
        float a0 = As[(arow + g)     * PAD + k0 + t];
        float a1 = As[(arow + g + 8) * PAD + k0 + t];
        float a2 = As[(arow + g)     * PAD + k0 + t + 4];
        float a3 = As[(arow + g + 8) * PAD + k0 + t + 4];
        uint32_t ab[4] = { f2tf32(a0), f2tf32(a1), f2tf32(a2), f2tf32(a3) };
        uint32_t ar[4] = { f2tf32(a0 - __uint_as_float(ab[0])),
                           f2tf32(a1 - __uint_as_float(ab[1])),
                           f2tf32(a2 - __uint_as_float(ab[2])),
                           f2tf32(a3 - __uint_as_float(ab[3])) };
        const float4* wrow = wf + (size_t)ks * (COUT * 4);
#pragma unroll
        for (int nt = 0; nt < NT; nt++) {
            int nb = nt * 8 + g;
            float4 f = __ldg(&wrow[nb * 4 + t]);
            uint32_t bb[2]  = { __float_as_uint(f.x), __float_as_uint(f.y) };
            uint32_t br2[2] = { __float_as_uint(f.z), __float_as_uint(f.w) };
            mma_tf32(acc[nt], ab, bb);
            mma_tf32(acc[nt], ab, br2);
            mma_tf32(acc[nt], ar, bb);
        }
    }

    int r0 = row0 + arow + g;
    int r1 = r0 + 8;
    float d0 = 1.f, d1 = 1.f;
    if (SCALE_EPI) {
        d0 = (r0 < n) ? g_dinv[r0] : 0.f;
        d1 = (r1 < n) ? g_dinv[r1] : 0.f;
    }
    __half* dst = g_xws16;
#pragma unroll
    for (int nt = 0; nt < NT; nt++) {
        int col = nt * 8 + t * 2;
        if (r0 < n) {
            __half2 hv = __floats2half2_rn(d0 * acc[nt][0], d0 * acc[nt][1]);
            *(__half2*)(dst + (size_t)r0 * COUT + col) = hv;
        }
        if (r1 < n) {
            __half2 hv = __floats2half2_rn(d1 * acc[nt][2], d1 * acc[nt][3]);
            *(__half2*)(dst + (size_t)r1 * COUT + col) = hv;
        }
    }
}

// ---------------------------------------------------------------------------
// Layer-1 GEMM: g_xws16 = half(x @ W1)  (UNSCALED; concurrent w/ preproc)
// ---------------------------------------------------------------------------
__global__ void __launch_bounds__(256)
k_gemm1(const float* __restrict__ X, const float4* __restrict__ wf, int n)
{
    constexpr int PAD = 132;
    extern __shared__ float As[];
    const int tid  = threadIdx.x;
    const int row0 = blockIdx.x * 128;

    for (int idx = tid; idx < 128 * (IN_C / 4); idx += 256) {
        int r  = idx / (IN_C / 4);
        int c4 = (idx - r * (IN_C / 4)) * 4;
        float4 v = make_float4(0.f, 0.f, 0.f, 0.f);
        if (row0 + r < n)
            v = *(const float4*)(X + (size_t)(row0 + r) * IN_C + c4);
        *(float4*)(As + r * PAD + c4) = v;
    }
    __syncthreads();
    mma_core<IN_C, HID_C, 0>(As, wf, row0, n, tid);
}

// ---------------------------------------------------------------------------
// Layer-2 GEMM: g_xws16 = half(dinv * (relu(g_agg1 + b1) @ W2))
// ---------------------------------------------------------------------------
__global__ void __launch_bounds__(256)
k_gemm2(const float4* __restrict__ wf, const float* __restrict__ b1, int n)
{
    constexpr int PAD = 132;
    extern __shared__ float As[];
    const int tid  = threadIdx.x;
    const int row0 = blockIdx.x * 128;

    for (int idx = tid; idx < 128 * (HID_C / 4); idx += 256) {
        int r  = idx / (HID_C / 4);
        int c4 = (idx - r * (HID_C / 4)) * 4;
        float4 v = make_float4(0.f, 0.f, 0.f, 0.f);
        if (row0 + r < n) {
            v = *(const float4*)(g_agg1 + (size_t)(row0 + r) * HID_C + c4);
            float4 b = *(const float4*)(b1 + c4);
            v.x = fmaxf(v.x + b.x, 0.f);
            v.y = fmaxf(v.y + b.y, 0.f);
            v.z = fmaxf(v.z + b.z, 0.f);
            v.w = fmaxf(v.w + b.w, 0.f);
        }
        *(float4*)(As + r * PAD + c4) = v;
    }
    __syncthreads();
    mma_core<HID_C, OUT_C, 1>(As, wf, row0, n, tid);
}

// ---------------------------------------------------------------------------
// Pull aggregation over fp16 features (8 B gathers), fp32 accumulation.
//   L==1: g_agg1[d] = dinv[d]*(sum_s dinv[s]*xw[s] + dinv[d]*xw[d])
//   L==2: out[d]    = b2 + dinv[d]*(sum + self)   (xw pre-scaled)
// LANES = C/4; each lane owns 4 channels = one uint2 (4 halves).
// ---------------------------------------------------------------------------
template <int C, int L>
__global__ void k_agg(float* __restrict__ extout, const float* __restrict__ b2,
                      int n)
{
    constexpr int LANES = C / 4;
    int node = blockIdx.x * blockDim.y + threadIdx.y;
    if (node >= n) return;
    int lane = threadIdx.x;

    const uint2* __restrict__ xw = (const uint2*)g_xws16;

    int beg = g_csr_off[node];
    int end = beg + g_deg[node];

    float dnode = g_dinv[node];

    // self-loop
    uint2 su = xw[(size_t)node * LANES + lane];
    float2 s0f = __half22float2(*(__half2*)&su.x);
    float2 s1f = __half22float2(*(__half2*)&su.y);
    float sw = (L == 1) ? dnode : 1.f;
    float ax = sw * s0f.x, ay = sw * s0f.y, az = sw * s1f.x, aw = sw * s1f.y;

    int j = beg;
    for (; j + 8 <= end; j += 8) {
        int i0 = g_csr_src[j + 0];
        int i1 = g_csr_src[j + 1];
        int i2 = g_csr_src[j + 2];
        int i3 = g_csr_src[j + 3];
        int i4 = g_csr_src[j + 4];
        int i5 = g_csr_src[j + 5];
        int i6 = g_csr_src[j + 6];
        int i7 = g_csr_src[j + 7];
        uint2 u0 = xw[(size_t)i0 * LANES + lane];
        uint2 u1 = xw[(size_t)i1 * LANES + lane];
        uint2 u2 = xw[(size_t)i2 * LANES + lane];
        uint2 u3 = xw[(size_t)i3 * LANES + lane];
        uint2 u4 = xw[(size_t)i4 * LANES + lane];
        uint2 u5 = xw[(size_t)i5 * LANES + lane];
        uint2 u6 = xw[(size_t)i6 * LANES + lane];
        uint2 u7 = xw[(size_t)i7 * LANES + lane];
        float w0 = 1.f, w1 = 1.f, w2 = 1.f, w3 = 1.f;
        float w4 = 1.f, w5 = 1.f, w6 = 1.f, w7 = 1.f;
        if (L == 1) {
            w0 = __ldg(&g_dinv[i0]); w1 = __ldg(&g_dinv[i1]);
            w2 = __ldg(&g_dinv[i2]); w3 = __ldg(&g_dinv[i3]);
            w4 = __ldg(&g_dinv[i4]); w5 = __ldg(&g_dinv[i5]);
            w6 = __ldg(&g_dinv[i6]); w7 = __ldg(&g_dinv[i7]);
        }
#define ACC1(u, wgt) do {                                    \
            float2 f0 = __half22float2(*(__half2*)&(u).x);   \
            float2 f1 = __half22float2(*(__half2*)&(u).y);   \
            ax += (wgt) * f0.x; ay += (wgt) * f0.y;          \
            az += (wgt) * f1.x; aw += (wgt) * f1.y;          \
        } while (0)
        ACC1(u0, w0); ACC1(u1, w1); ACC1(u2, w2); ACC1(u3, w3);
        ACC1(u4, w4); ACC1(u5, w5); ACC1(u6, w6); ACC1(u7, w7);
    }
    for (; j < end; ++j) {
        int s = g_csr_src[j];
        uint2 u = xw[(size_t)s * LANES + lane];
        float w = (L == 1) ? __ldg(&g_dinv[s]) : 1.f;
        ACC1(u, w);
    }
#undef ACC1

    if (L == 1) {
        float4 r;
        r.x = dnode * ax; r.y = dnode * ay;
        r.z = dnode * az; r.w = dnode * aw;
        ((float4*)g_agg1)[(size_t)node * LANES + lane] = r;
    } else {
        const float4 bb = ((const float4*)b2)[lane];
        float4 r;
        r.x = dnode * ax + bb.x;
        r.y = dnode * ay + bb.y;
        r.z = dnode * az + bb.z;
        r.w = dnode * aw + bb.w;
        ((float4*)extout)[(size_t)node * LANES + lane] = r;
    }
}

// ---------------------------------------------------------------------------
// Launch: round-14 proven structure (fork/join; NO post-join concurrency).
// ---------------------------------------------------------------------------
extern "C" void kernel_launch(void* const* d_in, const int* in_sizes, int n_in,
                              void* d_out, int out_size)
{
    const float* x  = (const float*)d_in[0];
    const void*  ei = d_in[1];
    const float* W1 = (const float*)d_in[2];
    const float* b1 = (const float*)d_in[3];
    const float* W2 = (const float*)d_in[4];
    const float* b2 = (const float*)d_in[5];
    float*       out = (float*)d_out;

    const int n = in_sizes[0] / IN_C;     // 100000
    const int e = in_sizes[1] / 2;        // 1600000
    const int TB = 256;
    const int nblk = (n + SCAN_B - 1) / SCAN_B;

    // One-time resources (init-only; per-call work is identical).
    static cudaStream_t s2 = nullptr;
    static cudaEvent_t evFork = nullptr, evJoin = nullptr;
    if (s2 == nullptr) {
        cudaStreamCreateWithFlags(&s2, cudaStreamNonBlocking);
        cudaEventCreateWithFlags(&evFork, cudaEventDisableTiming);
        cudaEventCreateWithFlags(&evJoin, cudaEventDisableTiming);
    }

    const int smemA = 128 * 132 * 4;      // 67584 B dynamic
    cudaFuncSetAttribute(k_gemm1,
                         cudaFuncAttributeMaxDynamicSharedMemorySize, smemA);
    cudaFuncSetAttribute(k_gemm2,
                         cudaFuncAttributeMaxDynamicSharedMemorySize, smemA);

    const int gblk = (n + 127) / 128;

    // ---- fork ----
    cudaEventRecord(evFork, 0);
    cudaStreamWaitEvent(s2, evFork, 0);

    // Stream B: merged weight split + GEMM1
    {
        const int tw = (IN_C / 8) * HID_C * 4 + (HID_C / 8) * OUT_C * 4;
        float4* wf1;  cudaGetSymbolAddress((void**)&wf1, g_wf1);
        k_wsplit_all<<<(tw + 255) / 256, 256, 0, s2>>>(W1, W2);
        k_gemm1<<<gblk, 256, smemA, s2>>>(x, wf1, n);
    }

    // Default stream: edge preprocessing
    k_init     <<<(n + TB - 1) / TB, TB>>>((const int*)ei, n);
    k_deg_count<<<(e / 2 + TB - 1) / TB, TB>>>(ei, e);
    k_scanA    <<<nblk, SCAN_B>>>(n);
    k_scanB    <<<1, 512>>>(nblk);
    k_scanC    <<<nblk, SCAN_B>>>(n);
    k_csr_build<<<(e / 2 + TB - 1) / TB, TB>>>(ei, e);

    // ---- join ----
    cudaEventRecord(evJoin, s2);
    cudaStreamWaitEvent(0, evJoin, 0);

    // Layer 1 aggregation (alone, full L2 bandwidth; fp16 gathers)
    {
        dim3 blk(HID_C / 4, 8);
        k_agg<HID_C, 1><<<(n + 7) / 8, blk>>>(nullptr, nullptr, n);
    }

    // Layer 2
    {
        float4* wf2;  cudaGetSymbolAddress((void**)&wf2, g_wf2);
        k_gemm2<<<gblk, 256, smemA>>>(wf2, b1, n);
    }
    {
        dim3 blk(OUT_C / 4, 16);
        k_agg<OUT_C, 2><<<(n + 15) / 16, blk>>>(out, b2, n);
    }
}